// round 3
// baseline (speedup 1.0000x reference)
#include <cuda_runtime.h>
#include <cuda_bf16.h>
#include <math.h>

#define S_LEN 2048
#define DIMM 1024
#define NHEADS 16
#define HEADD 64
#define FFN_HH 4096
#define LEXP 8
#define TOPKK 2
#define DIM_EE 512
#define DIM_SS 1024
#define NPAIR (S_LEN*TOPKK)
#define NMOE_L 2

// ---------------- scratch (device globals; no allocation allowed) ----------------
__device__ float g_xn[S_LEN*DIMM];
__device__ float g_qkv[S_LEN*3*DIMM];
__device__ float g_attn[S_LEN*DIMM];
__device__ float g_proj[S_LEN*DIMM];
__device__ float g_xi[S_LEN*DIMM];
__device__ float g_xf[S_LEN*DIMM];
__device__ float g_u[S_LEN*2*FFN_HH];
__device__ float g_hh[S_LEN*FFN_HH];
__device__ float g_ffn[S_LEN*DIMM];
__device__ float g_xbuf[S_LEN*DIMM];
__device__ float g_tv[S_LEN*LEXP];
__device__ int   g_dstart[S_LEN];
__device__ int   g_route_e[NPAIR];
__device__ float g_route_sc[NPAIR];
__device__ int   g_pair_tok[NPAIR];
__device__ int   g_pair_pos[NPAIR];
__device__ int   g_cnt[LEXP];
__device__ int   g_off[LEXP];
__device__ int   g_fill[LEXP];
__device__ int   g_idx_is32;
__device__ float g_eh1[NPAIR*DIM_EE];
__device__ float g_eh2[NPAIR*DIM_EE];
__device__ float g_ey[NPAIR*DIMM];

// device pointer table: selectors for reusable kernels (no cudaGetSymbolAddress)
#define SEL_XN   0
#define SEL_QKV  1
#define SEL_ATTN 2
#define SEL_PROJ 3
#define SEL_XI   4
#define SEL_XF   5
#define SEL_U    6
#define SEL_HH   7
#define SEL_FFN  8
#define SEL_XBUF 9
__device__ float* g_ptab[10];

__global__ void init_ptab_kernel() {
    if (threadIdx.x == 0) {
        g_ptab[SEL_XN]   = g_xn;
        g_ptab[SEL_QKV]  = g_qkv;
        g_ptab[SEL_ATTN] = g_attn;
        g_ptab[SEL_PROJ] = g_proj;
        g_ptab[SEL_XI]   = g_xi;
        g_ptab[SEL_XF]   = g_xf;
        g_ptab[SEL_U]    = g_u;
        g_ptab[SEL_FFN]  = g_ffn;
        g_ptab[SEL_HH]   = g_hh;
        g_ptab[SEL_XBUF] = g_xbuf;
    }
}

__device__ __forceinline__ const float* rsel(const float* ext, int sel) {
    return sel >= 0 ? (const float*)g_ptab[sel] : ext;
}
__device__ __forceinline__ float* wsel(float* ext, int sel) {
    return sel >= 0 ? g_ptab[sel] : ext;
}

// ---------------- index dtype detection ----------------
// If indices are int64 (LE) with small values, every odd 32-bit word in the
// first NMOE*NPAIR words is a zero high-half. If int32, those words are real
// indices (uniform 0..7) and are nonzero with overwhelming probability.
__global__ void detect_idx_kernel(const int* __restrict__ idx32) {
    __shared__ int any;
    if (threadIdx.x == 0) any = 0;
    __syncthreads();
    int loc = 0;
    for (int i = threadIdx.x; i < NMOE_L * NPAIR; i += blockDim.x)
        if (i & 1) loc |= idx32[i];
    if (loc) atomicOr(&any, 1);
    __syncthreads();
    if (threadIdx.x == 0) g_idx_is32 = (any != 0);
}

// ---------------- generic SGEMM: C = A(MxK,rm) @ B(KxN,rm) ----------------
__global__ void sgemm_nn(int Asel, const float* __restrict__ B, int Csel,
                         int M, int N, int K) {
    const float* A = (const float*)g_ptab[Asel];
    float* C = g_ptab[Csel];
    __shared__ float As[8][128];
    __shared__ float Bs[8][128];
    const int row0 = blockIdx.y * 128;
    const int col0 = blockIdx.x * 128;
    const int tid = threadIdx.x;
    const int tx = tid & 15, ty = tid >> 4;
    const int arow = tid >> 1, acol = (tid & 1) * 4;
    const int brow = tid >> 5, bcol = (tid & 31) * 4;
    float acc[8][8] = {};
    for (int k0 = 0; k0 < K; k0 += 8) {
        float4 av = *(const float4*)(A + (size_t)(row0 + arow) * K + k0 + acol);
        As[acol + 0][arow] = av.x; As[acol + 1][arow] = av.y;
        As[acol + 2][arow] = av.z; As[acol + 3][arow] = av.w;
        float4 bv = *(const float4*)(B + (size_t)(k0 + brow) * N + col0 + bcol);
        *(float4*)&Bs[brow][bcol] = bv;
        __syncthreads();
#pragma unroll
        for (int k = 0; k < 8; k++) {
            float ra[8], rb[8];
#pragma unroll
            for (int i = 0; i < 8; i++) ra[i] = As[k][ty * 8 + i];
#pragma unroll
            for (int j = 0; j < 8; j++) rb[j] = Bs[k][tx * 8 + j];
#pragma unroll
            for (int i = 0; i < 8; i++)
#pragma unroll
                for (int j = 0; j < 8; j++) acc[i][j] += ra[i] * rb[j];
        }
        __syncthreads();
    }
#pragma unroll
    for (int i = 0; i < 8; i++) {
        float* cp = C + (size_t)(row0 + ty * 8 + i) * N + col0 + tx * 8;
        *(float4*)cp       = make_float4(acc[i][0], acc[i][1], acc[i][2], acc[i][3]);
        *(float4*)(cp + 4) = make_float4(acc[i][4], acc[i][5], acc[i][6], acc[i][7]);
    }
}

// ---------------- expert GEMM (gathered A rows = g_xf, per-expert weight), NN ----------------
__global__ void expert_gemm_nn(const float* __restrict__ W, int csel, int K, int N) {
    const float* flat = g_xf;
    float* C = csel == 0 ? g_eh1 : g_eh2;
    const int RB = NPAIR / 128;
    int e = blockIdx.y / RB;
    int rb = blockIdx.y % RB;
    int c = g_cnt[e];
    int local0 = rb * 128;
    if (local0 >= c) return;
    int base = g_off[e];
    const float* We = W + (size_t)e * K * N;
    __shared__ float As[8][128];
    __shared__ float Bs[8][128];
    __shared__ int rowtok[128];
    const int tid = threadIdx.x;
    if (tid < 128) {
        int lr = local0 + tid;
        int pr = base + min(lr, c - 1);
        rowtok[tid] = g_pair_tok[pr];
    }
    __syncthreads();
    const int tx = tid & 15, ty = tid >> 4;
    const int arow = tid >> 1, acol = (tid & 1) * 4;
    const int brow = tid >> 5, bcol = (tid & 31) * 4;
    const int col0 = blockIdx.x * 128;
    float acc[8][8] = {};
    for (int k0 = 0; k0 < K; k0 += 8) {
        float4 av = *(const float4*)(flat + (size_t)rowtok[arow] * K + k0 + acol);
        As[acol + 0][arow] = av.x; As[acol + 1][arow] = av.y;
        As[acol + 2][arow] = av.z; As[acol + 3][arow] = av.w;
        float4 bv = *(const float4*)(We + (size_t)(k0 + brow) * N + col0 + bcol);
        *(float4*)&Bs[brow][bcol] = bv;
        __syncthreads();
#pragma unroll
        for (int k = 0; k < 8; k++) {
            float ra[8], rb[8];
#pragma unroll
            for (int i = 0; i < 8; i++) ra[i] = As[k][ty * 8 + i];
#pragma unroll
            for (int j = 0; j < 8; j++) rb[j] = Bs[k][tx * 8 + j];
#pragma unroll
            for (int i = 0; i < 8; i++)
#pragma unroll
                for (int j = 0; j < 8; j++) acc[i][j] += ra[i] * rb[j];
        }
        __syncthreads();
    }
#pragma unroll
    for (int i = 0; i < 8; i++) {
        int lr = local0 + ty * 8 + i;
        if (lr < c) {
            float* cp = C + (size_t)(base + lr) * N + col0 + tx * 8;
            *(float4*)cp       = make_float4(acc[i][0], acc[i][1], acc[i][2], acc[i][3]);
            *(float4*)(cp + 4) = make_float4(acc[i][4], acc[i][5], acc[i][6], acc[i][7]);
        }
    }
}

// ---------------- expert down-proj: g_ey[r,n] = sum_k g_eh1[r,k] * W[e][n,k] (NT) ----------------
__global__ void expert_gemm_nt(const float* __restrict__ W, int K, int N) {
    const float* act = g_eh1;
    float* C = g_ey;
    const int RB = NPAIR / 128;
    int e = blockIdx.y / RB;
    int rb = blockIdx.y % RB;
    int c = g_cnt[e];
    int local0 = rb * 128;
    if (local0 >= c) return;
    int base = g_off[e];
    const float* We = W + (size_t)e * N * K;
    __shared__ float As[8][128];
    __shared__ float Bs[8][128];
    const int tid = threadIdx.x;
    const int tx = tid & 15, ty = tid >> 4;
    const int arow = tid >> 1, acol = (tid & 1) * 4;
    const int bn = tid >> 1, bkc = (tid & 1) * 4;
    const int col0 = blockIdx.x * 128;
    float acc[8][8] = {};
    int arow_g = base + min(local0 + arow, c - 1);
    for (int k0 = 0; k0 < K; k0 += 8) {
        float4 av = *(const float4*)(act + (size_t)arow_g * K + k0 + acol);
        As[acol + 0][arow] = av.x; As[acol + 1][arow] = av.y;
        As[acol + 2][arow] = av.z; As[acol + 3][arow] = av.w;
        float4 bv = *(const float4*)(We + (size_t)(col0 + bn) * K + k0 + bkc);
        Bs[bkc + 0][bn] = bv.x; Bs[bkc + 1][bn] = bv.y;
        Bs[bkc + 2][bn] = bv.z; Bs[bkc + 3][bn] = bv.w;
        __syncthreads();
#pragma unroll
        for (int k = 0; k < 8; k++) {
            float ra[8], rbv[8];
#pragma unroll
            for (int i = 0; i < 8; i++) ra[i] = As[k][ty * 8 + i];
#pragma unroll
            for (int j = 0; j < 8; j++) rbv[j] = Bs[k][tx * 8 + j];
#pragma unroll
            for (int i = 0; i < 8; i++)
#pragma unroll
                for (int j = 0; j < 8; j++) acc[i][j] += ra[i] * rbv[j];
        }
        __syncthreads();
    }
#pragma unroll
    for (int i = 0; i < 8; i++) {
        int lr = local0 + ty * 8 + i;
        if (lr < c) {
            float* cp = C + (size_t)(base + lr) * N + col0 + tx * 8;
            *(float4*)cp       = make_float4(acc[i][0], acc[i][1], acc[i][2], acc[i][3]);
            *(float4*)(cp + 4) = make_float4(acc[i][4], acc[i][5], acc[i][6], acc[i][7]);
        }
    }
}

// ---------------- elementwise / norm / attention helpers ----------------
__global__ void rmsnorm_kernel(const float* xext, int xsel,
                               const float* __restrict__ g, int ysel) {
    const float* x = rsel(xext, xsel);
    float* y = g_ptab[ysel];
    int r = blockIdx.x, t = threadIdx.x;
    const float* xr = x + (size_t)r * DIMM;
    float s = 0.f;
    for (int i = t; i < DIMM; i += 256) { float v = xr[i]; s += v * v; }
    __shared__ float red[8];
    for (int o = 16; o; o >>= 1) s += __shfl_xor_sync(~0u, s, o);
    if ((t & 31) == 0) red[t >> 5] = s;
    __syncthreads();
    __shared__ float tot;
    if (t == 0) {
        float v = 0.f;
        for (int i = 0; i < 8; i++) v += red[i];
        tot = rsqrtf(v / DIMM + 1e-6f);
    }
    __syncthreads();
    float rr = tot;
    float* yr = y + (size_t)r * DIMM;
    for (int i = t; i < DIMM; i += 256) yr[i] = xr[i] * rr * g[i];
}

__global__ void add_kernel(int asel, const float* bext, int bsel,
                           float* cext, int csel, int n) {
    const float* a = (const float*)g_ptab[asel];
    const float* b = rsel(bext, bsel);
    float* c = wsel(cext, csel);
    int i = blockIdx.x * blockDim.x + threadIdx.x;
    if (i < n) c[i] = a[i] + b[i];
}

// g_u -> g_hh
__global__ void swiglu_kernel(int H, int total) {
    int i = blockIdx.x * blockDim.x + threadIdx.x;
    if (i >= total) return;
    int r = i / H, cidx = i - r * H;
    float a = g_u[(size_t)r * 2 * H + cidx];
    float b = g_u[(size_t)r * 2 * H + H + cidx];
    g_hh[i] = a / (1.f + expf(-a)) * b;
}

__global__ void swiglu_pair_kernel(int total) {
    int i = blockIdx.x * blockDim.x + threadIdx.x;
    if (i >= total) return;
    float a = g_eh1[i], b = g_eh2[i];
    g_eh1[i] = a / (1.f + expf(-a)) * b;
}

__global__ void doc_start_kernel(const int* __restrict__ doc) {
    int s = blockIdx.x * blockDim.x + threadIdx.x;
    if (s >= S_LEN) return;
    int v = doc[s];
    int lo = 0, hi = s;
    while (lo < hi) { int mid = (lo + hi) >> 1; if (doc[mid] < v) lo = mid + 1; else hi = mid; }
    g_dstart[s] = lo;
}

__global__ void rotary_kernel() {
    int s = blockIdx.x, h = blockIdx.y, i = threadIdx.x;  // i in [0,32)
    double invf = pow(10000.0, -((double)(2 * i)) / (double)HEADD);
    double fr = (double)s * invf;
    float c = (float)cos(fr), sn = (float)sin(fr);
    float* q = g_qkv + (size_t)s * 3 * DIMM + h * HEADD;
    float* k = q + DIMM;
    float x1 = q[i], x2 = q[i + 32];
    q[i] = x1 * c + x2 * sn; q[i + 32] = -x1 * sn + x2 * c;
    x1 = k[i]; x2 = k[i + 32];
    k[i] = x1 * c + x2 * sn; k[i + 32] = -x1 * sn + x2 * c;
}

// flash-style attention: block = (64 queries, 1 head); 1 thread per query.
__global__ void flash_kernel() {
    int h = blockIdx.y;
    int q0 = blockIdx.x * 64;
    int t = threadIdx.x;
    int sq = q0 + t;
    __shared__ float Ks[64][64];
    __shared__ float Vs[64][64];
    float qreg[64];
    const float* qp = g_qkv + (size_t)sq * 3 * DIMM + h * HEADD;
#pragma unroll
    for (int d = 0; d < 64; d++) qreg[d] = qp[d];
    float m = -1e30f, l = 0.f;
    float acc[64];
#pragma unroll
    for (int d = 0; d < 64; d++) acc[d] = 0.f;
    int ds = g_dstart[sq];
    int t0 = g_dstart[q0] >> 6;
    for (int kt = t0; kt <= (int)blockIdx.x; kt++) {
        int kbase = kt * 64;
        for (int idx = t; idx < 64 * 64; idx += 64) {
            int r = idx >> 6, d = idx & 63;
            const float* kv = g_qkv + (size_t)(kbase + r) * 3 * DIMM + h * HEADD + d;
            Ks[r][d] = kv[DIMM];
            Vs[r][d] = kv[2 * DIMM];
        }
        __syncthreads();
        int jmax = min(63, sq - kbase);
        int jmin = max(0, ds - kbase);
        for (int j = jmin; j <= jmax; j++) {
            float s0 = 0.f, s1 = 0.f, s2 = 0.f, s3 = 0.f;
#pragma unroll
            for (int d = 0; d < 64; d += 4) {
                s0 += qreg[d] * Ks[j][d];
                s1 += qreg[d + 1] * Ks[j][d + 1];
                s2 += qreg[d + 2] * Ks[j][d + 2];
                s3 += qreg[d + 3] * Ks[j][d + 3];
            }
            float s = (s0 + s1 + s2 + s3) * 0.125f;
            float mn = fmaxf(m, s);
            float corr = __expf(m - mn);
            float p = __expf(s - mn);
            l = l * corr + p;
#pragma unroll
            for (int d = 0; d < 64; d++) acc[d] = acc[d] * corr + p * Vs[j][d];
            m = mn;
        }
        __syncthreads();
    }
    float inv = 1.f / l;
    float* op = g_attn + (size_t)sq * DIMM + h * HEADD;
#pragma unroll
    for (int d = 0; d < 64; d++) op[d] = acc[d] * inv;
}

// ---------------- MoE routing ----------------
__global__ void tv_kernel(const float* __restrict__ tkeys) {
    int n = blockIdx.x;
    int w = threadIdx.x >> 5, lane = threadIdx.x & 31;
    const float* xr = g_xf + (size_t)n * DIMM;
    float s = 0.f;
    for (int d = lane; d < DIMM; d += 32) s += xr[d] * tkeys[d * LEXP + w];
    for (int o = 16; o; o >>= 1) s += __shfl_xor_sync(~0u, s, o);
    if (lane == 0) g_tv[n * LEXP + w] = s;
}

__global__ void zero_cnt_kernel() {
    if (threadIdx.x < LEXP) g_cnt[threadIdx.x] = 0;
}

// idx32: base pointer to indices reinterpreted as int32; off = element offset
__global__ void route1_kernel(const int* __restrict__ idx32, int off,
                              const float* __restrict__ vals,
                              const float* __restrict__ rbias) {
    int n = blockIdx.x * blockDim.x + threadIdx.x;
    if (n >= S_LEN) return;
    int is32 = g_idx_is32;
    float sc[TOPKK]; int e[TOPKK];
    float sum = 0.f;
#pragma unroll
    for (int k = 0; k < TOPKK; k++) {
        int elem = off + n * TOPKK + k;
        int ei = is32 ? idx32[elem] : idx32[2 * elem];  // int64 LE: low word
        e[k] = min(max(ei, 0), LEXP - 1);
        float v = vals[(size_t)n * TOPKK + k] + g_tv[n * LEXP + e[k]] + rbias[e[k]];
        sc[k] = 1.f / (1.f + expf(-v));
        sum += sc[k];
    }
#pragma unroll
    for (int k = 0; k < TOPKK; k++) {
        g_route_e[n * TOPKK + k] = e[k];
        g_route_sc[n * TOPKK + k] = sc[k] / sum;
        atomicAdd(&g_cnt[e[k]], 1);
    }
}

__global__ void scan_kernel() {
    int o = 0;
    for (int e = 0; e < LEXP; e++) { g_off[e] = o; o += g_cnt[e]; g_fill[e] = 0; }
}

__global__ void route2_kernel() {
    int n = blockIdx.x * blockDim.x + threadIdx.x;
    if (n >= S_LEN) return;
#pragma unroll
    for (int k = 0; k < TOPKK; k++) {
        int e = g_route_e[n * TOPKK + k];
        int slot = atomicAdd(&g_fill[e], 1);
        int pos = g_off[e] + slot;
        g_pair_tok[pos] = n;
        g_pair_pos[n * TOPKK + k] = pos;
    }
}

// xbuf = expert mix + g_ffn(shared) + g_xi
__global__ void moe_final_kernel() {
    int i = blockIdx.x * blockDim.x + threadIdx.x;
    if (i >= S_LEN * DIMM) return;
    int n = i >> 10, d = i & 1023;
    int p0 = g_pair_pos[2 * n], p1 = g_pair_pos[2 * n + 1];
    float y = g_route_sc[2 * n] * g_ey[(size_t)p0 * DIMM + d]
            + g_route_sc[2 * n + 1] * g_ey[(size_t)p1 * DIMM + d];
    g_xbuf[i] = y + g_ffn[i] + g_xi[i];
}

// ---------------- host orchestration ----------------
extern "C" void kernel_launch(void* const* d_in, const int* in_sizes, int n_in,
                              void* d_out, int out_size) {
    const float* x       = (const float*)d_in[0];
    const int*   doc     = (const int*)d_in[1];
    const int*   idx32   = (const int*)d_in[2];   // dtype-agnostic view
    const float* values  = (const float*)d_in[3];
    const float* daw     = (const float*)d_in[4];
    const float* dao     = (const float*)d_in[5];
    const float* dup     = (const float*)d_in[6];
    const float* ddown   = (const float*)d_in[7];
    const float* dag     = (const float*)d_in[8];
    const float* dfg     = (const float*)d_in[9];
    const float* mawp    = (const float*)d_in[10];
    const float* maop    = (const float*)d_in[11];
    const float* magp    = (const float*)d_in[12];
    const float* mfgp    = (const float*)d_in[13];
    const float* experts = (const float*)d_in[14];
    const float* mtk     = (const float*)d_in[15];
    const float* rbias   = (const float*)d_in[16];
    const float* sup     = (const float*)d_in[17];
    const float* sdown   = (const float*)d_in[18];

    const int ND = S_LEN * DIMM;

    init_ptab_kernel<<<1, 32>>>();
    detect_idx_kernel<<<1, 256>>>(idx32);
    doc_start_kernel<<<(S_LEN + 255) / 256, 256>>>(doc);

    auto gemm = [&](int Asel, const float* B, int Csel, int M, int N, int K) {
        dim3 grid(N / 128, M / 128);
        sgemm_nn<<<grid, 256>>>(Asel, B, Csel, M, N, K);
    };
    auto attn_block = [&](const float* Xext, int Xsel, const float* aw,
                          const float* ao, const float* ag) {
        rmsnorm_kernel<<<S_LEN, 256>>>(Xext, Xsel, ag, SEL_XN);
        gemm(SEL_XN, aw, SEL_QKV, S_LEN, 3 * DIMM, DIMM);
        rotary_kernel<<<dim3(S_LEN, NHEADS), 32>>>();
        flash_kernel<<<dim3(S_LEN / 64, NHEADS), 64>>>();
        gemm(SEL_ATTN, ao, SEL_PROJ, S_LEN, DIMM, DIMM);
        add_kernel<<<(ND + 255) / 256, 256>>>(SEL_PROJ, Xext, Xsel, nullptr, SEL_XI, ND);
    };

    // ---- dense layer 0 ----
    {
        int li = 0;
        attn_block(x, -1, daw + (size_t)li * DIMM * 3 * DIMM,
                   dao + (size_t)li * DIMM * DIMM, dag + (size_t)li * DIMM);
        rmsnorm_kernel<<<S_LEN, 256>>>(nullptr, SEL_XI, dfg + (size_t)li * DIMM, SEL_XF);
        gemm(SEL_XF, dup + (size_t)li * DIMM * 2 * FFN_HH, SEL_U, S_LEN, 2 * FFN_HH, DIMM);
        swiglu_kernel<<<(S_LEN * FFN_HH + 255) / 256, 256>>>(FFN_HH, S_LEN * FFN_HH);
        gemm(SEL_HH, ddown + (size_t)li * FFN_HH * DIMM, SEL_FFN, S_LEN, DIMM, FFN_HH);
        add_kernel<<<(ND + 255) / 256, 256>>>(SEL_FFN, nullptr, SEL_XI, nullptr, SEL_XBUF, ND);
    }

    // ---- MoE layers ----
    for (int li = 0; li < 2; li++) {
        attn_block(nullptr, SEL_XBUF, mawp + (size_t)li * DIMM * 3 * DIMM,
                   maop + (size_t)li * DIMM * DIMM, magp + (size_t)li * DIMM);
        rmsnorm_kernel<<<S_LEN, 256>>>(nullptr, SEL_XI, mfgp + (size_t)li * DIMM, SEL_XF);
        tv_kernel<<<S_LEN, 256>>>(mtk + (size_t)li * DIMM * LEXP);
        zero_cnt_kernel<<<1, 32>>>();
        route1_kernel<<<(S_LEN + 255) / 256, 256>>>(idx32, li * NPAIR,
                                                    values + (size_t)li * NPAIR,
                                                    rbias + (size_t)li * LEXP);
        scan_kernel<<<1, 1>>>();
        route2_kernel<<<(S_LEN + 255) / 256, 256>>>();
        const float* eb = experts + (size_t)li * 3 * LEXP * DIMM * DIM_EE;
        dim3 eg_up(DIM_EE / 128, LEXP * (NPAIR / 128));
        expert_gemm_nn<<<eg_up, 256>>>(eb, 0, DIMM, DIM_EE);
        expert_gemm_nn<<<eg_up, 256>>>(eb + (size_t)LEXP * DIMM * DIM_EE, 1, DIMM, DIM_EE);
        swiglu_pair_kernel<<<(NPAIR * DIM_EE + 255) / 256, 256>>>(NPAIR * DIM_EE);
        dim3 eg_dn(DIMM / 128, LEXP * (NPAIR / 128));
        expert_gemm_nt<<<eg_dn, 256>>>(eb + (size_t)2 * LEXP * DIMM * DIM_EE, DIM_EE, DIMM);
        // shared expert
        gemm(SEL_XF, sup + (size_t)li * DIMM * 2 * DIM_SS, SEL_U, S_LEN, 2 * DIM_SS, DIMM);
        swiglu_kernel<<<(S_LEN * DIM_SS + 255) / 256, 256>>>(DIM_SS, S_LEN * DIM_SS);
        gemm(SEL_HH, sdown + (size_t)li * DIM_SS * DIMM, SEL_FFN, S_LEN, DIMM, DIM_SS);
        moe_final_kernel<<<(ND + 255) / 256, 256>>>();
    }

    // ---- dense layer 1 (writes d_out) ----
    {
        int li = 1;
        attn_block(nullptr, SEL_XBUF, daw + (size_t)li * DIMM * 3 * DIMM,
                   dao + (size_t)li * DIMM * DIMM, dag + (size_t)li * DIMM);
        rmsnorm_kernel<<<S_LEN, 256>>>(nullptr, SEL_XI, dfg + (size_t)li * DIMM, SEL_XF);
        gemm(SEL_XF, dup + (size_t)li * DIMM * 2 * FFN_HH, SEL_U, S_LEN, 2 * FFN_HH, DIMM);
        swiglu_kernel<<<(S_LEN * FFN_HH + 255) / 256, 256>>>(FFN_HH, S_LEN * FFN_HH);
        gemm(SEL_HH, ddown + (size_t)li * FFN_HH * DIMM, SEL_FFN, S_LEN, DIMM, FFN_HH);
        add_kernel<<<(ND + 255) / 256, 256>>>(SEL_FFN, nullptr, SEL_XI, (float*)d_out, -1, ND);
    }
}

// round 4
// speedup vs baseline: 2.1694x; 2.1694x over previous
#include <cuda_runtime.h>
#include <cuda_bf16.h>
#include <math.h>
#include <stdint.h>

#define S_LEN 2048
#define DIMM 1024
#define NHEADS 16
#define HEADD 64
#define FFN_HH 4096
#define LEXP 8
#define TOPKK 2
#define DIM_EE 512
#define DIM_SS 1024
#define NPAIR (S_LEN*TOPKK)
#define NMOE_L 2

// ---------------- scratch (device globals; no allocation allowed) ----------------
__device__ float g_xn[S_LEN*DIMM];
__device__ float g_qkv[S_LEN*3*DIMM];
__device__ float g_attn[S_LEN*DIMM];
__device__ float g_proj[S_LEN*DIMM];
__device__ float g_xi[S_LEN*DIMM];
__device__ float g_xf[S_LEN*DIMM];
__device__ float g_u[S_LEN*2*FFN_HH];
__device__ float g_hh[S_LEN*FFN_HH];
__device__ float g_ffn[S_LEN*DIMM];
__device__ float g_xbuf[S_LEN*DIMM];
__device__ float g_tv[S_LEN*LEXP];
__device__ int   g_dstart[S_LEN];
__device__ int   g_route_e[NPAIR];
__device__ float g_route_sc[NPAIR];
__device__ int   g_pair_tok[NPAIR];
__device__ int   g_pair_pos[NPAIR];
__device__ int   g_cnt[LEXP];
__device__ int   g_off[LEXP];
__device__ int   g_fill[LEXP];
__device__ int   g_idx_is32;
__device__ float g_eh1[NPAIR*DIM_EE];
__device__ float g_eh2[NPAIR*DIM_EE];
__device__ float g_ey[NPAIR*DIMM];

#define SEL_XN   0
#define SEL_QKV  1
#define SEL_ATTN 2
#define SEL_PROJ 3
#define SEL_XI   4
#define SEL_XF   5
#define SEL_U    6
#define SEL_HH   7
#define SEL_FFN  8
#define SEL_XBUF 9
__device__ float* g_ptab[10];

__global__ void init_ptab_kernel() {
    if (threadIdx.x == 0) {
        g_ptab[SEL_XN]   = g_xn;
        g_ptab[SEL_QKV]  = g_qkv;
        g_ptab[SEL_ATTN] = g_attn;
        g_ptab[SEL_PROJ] = g_proj;
        g_ptab[SEL_XI]   = g_xi;
        g_ptab[SEL_XF]   = g_xf;
        g_ptab[SEL_U]    = g_u;
        g_ptab[SEL_FFN]  = g_ffn;
        g_ptab[SEL_HH]   = g_hh;
        g_ptab[SEL_XBUF] = g_xbuf;
    }
}

__device__ __forceinline__ const float* rsel(const float* ext, int sel) {
    return sel >= 0 ? (const float*)g_ptab[sel] : ext;
}
__device__ __forceinline__ float* wsel(float* ext, int sel) {
    return sel >= 0 ? g_ptab[sel] : ext;
}

// ---------------- TF32 MMA helpers ----------------
__device__ __forceinline__ uint32_t f2tf32(float f) {
    uint32_t u;
    asm("cvt.rna.tf32.f32 %0, %1;" : "=r"(u) : "f"(f));
    return u;
}

__device__ __forceinline__ void mma_tf32(float* d, const uint32_t* a, const uint32_t* b) {
    asm volatile(
        "mma.sync.aligned.m16n8k8.row.col.f32.tf32.tf32.f32 "
        "{%0,%1,%2,%3}, {%4,%5,%6,%7}, {%8,%9}, {%0,%1,%2,%3};\n"
        : "+f"(d[0]), "+f"(d[1]), "+f"(d[2]), "+f"(d[3])
        : "r"(a[0]), "r"(a[1]), "r"(a[2]), "r"(a[3]), "r"(b[0]), "r"(b[1]));
}

#define SA 136   // smem row stride (words); 136 % 32 == 8 -> conflict-free frag loads
#define SB 136

// warp computes 64x32 using 16 k=8 MMAs per k8-step, BK=16
__device__ __forceinline__ void warp_compute16(const uint32_t* As, const uint32_t* Bs,
                                               float (*d)[4][4], int mbase, int nbase,
                                               int g, int t) {
#pragma unroll
    for (int km = 0; km < 16; km += 8) {
        uint32_t af[4][4], bf[4][2];
#pragma unroll
        for (int i = 0; i < 4; i++) {
            const uint32_t* a0p = As + (km + t) * SA + mbase + i * 16 + g;
            const uint32_t* a1p = As + (km + t + 4) * SA + mbase + i * 16 + g;
            af[i][0] = a0p[0]; af[i][1] = a0p[8];
            af[i][2] = a1p[0]; af[i][3] = a1p[8];
        }
#pragma unroll
        for (int j = 0; j < 4; j++) {
            bf[j][0] = Bs[(km + t) * SB + nbase + j * 8 + g];
            bf[j][1] = Bs[(km + t + 4) * SB + nbase + j * 8 + g];
        }
#pragma unroll
        for (int i = 0; i < 4; i++)
#pragma unroll
            for (int j = 0; j < 4; j++)
                mma_tf32(d[i][j], af[i], bf[j]);
    }
}

// ---------------- TF32 GEMM: C = A(MxK,rm) @ B(KxN,rm) ----------------
__global__ __launch_bounds__(256) void mma_gemm_nn(int Asel, const float* __restrict__ B,
                                                   int Csel, int M, int N, int K) {
    const float* A = (const float*)g_ptab[Asel];
    float* C = g_ptab[Csel];
    __shared__ __align__(16) uint32_t As[2][16 * SA];
    __shared__ __align__(16) uint32_t Bs[2][16 * SB];
    const int tid = threadIdx.x;
    const int lane = tid & 31, wid = tid >> 5;
    const int g = lane >> 2, t = lane & 3;
    const int warp_m = wid >> 2, warp_n = wid & 3;
    const int row0 = blockIdx.y * 128, col0 = blockIdx.x * 128;

    float4 va[2], vb[2];
    auto loadA = [&](int k0) {
#pragma unroll
        for (int l = 0; l < 2; l++) {
            int f = tid + l * 256;
            int row = f >> 2, kc = (f & 3) * 4;
            va[l] = *(const float4*)(A + (size_t)(row0 + row) * K + k0 + kc);
        }
    };
    auto loadB = [&](int k0) {
#pragma unroll
        for (int l = 0; l < 2; l++) {
            int f = tid + l * 256;
            int r = f >> 5, nc = (f & 31) * 4;
            vb[l] = *(const float4*)(B + (size_t)(k0 + r) * N + col0 + nc);
        }
    };
    auto stage = [&](int buf) {
#pragma unroll
        for (int l = 0; l < 2; l++) {
            int f = tid + l * 256;
            int row = f >> 2, kc = (f & 3) * 4;
            As[buf][(kc + 0) * SA + row] = f2tf32(va[l].x);
            As[buf][(kc + 1) * SA + row] = f2tf32(va[l].y);
            As[buf][(kc + 2) * SA + row] = f2tf32(va[l].z);
            As[buf][(kc + 3) * SA + row] = f2tf32(va[l].w);
        }
#pragma unroll
        for (int l = 0; l < 2; l++) {
            int f = tid + l * 256;
            int r = f >> 5, nc = (f & 31) * 4;
            uint4 u = make_uint4(f2tf32(vb[l].x), f2tf32(vb[l].y),
                                 f2tf32(vb[l].z), f2tf32(vb[l].w));
            *(uint4*)&Bs[buf][r * SB + nc] = u;
        }
    };

    float d[4][4][4] = {};
    const int NIT = K / 16;
    loadA(0); loadB(0);
    stage(0);
    __syncthreads();
    int buf = 0;
    for (int it = 0; it < NIT; it++) {
        if (it + 1 < NIT) { loadA((it + 1) * 16); loadB((it + 1) * 16); }
        warp_compute16(As[buf], Bs[buf], d, warp_m * 64, warp_n * 32, g, t);
        if (it + 1 < NIT) {
            stage(buf ^ 1);
            __syncthreads();
            buf ^= 1;
        }
    }

    const int row_base = row0 + warp_m * 64, col_base = col0 + warp_n * 32;
#pragma unroll
    for (int i = 0; i < 4; i++)
#pragma unroll
        for (int j = 0; j < 4; j++) {
            int r = row_base + i * 16 + g;
            int cc = col_base + j * 8 + 2 * t;
            *(float2*)&C[(size_t)r * N + cc]       = make_float2(d[i][j][0], d[i][j][1]);
            *(float2*)&C[(size_t)(r + 8) * N + cc] = make_float2(d[i][j][2], d[i][j][3]);
        }
}

// ---------------- expert GEMM NN (gathered rows from g_xf) ----------------
__global__ __launch_bounds__(256) void mma_expert_nn(const float* __restrict__ W, int csel,
                                                     int K, int N) {
    const float* flat = g_xf;
    float* C = csel == 0 ? g_eh1 : g_eh2;
    const int RB = NPAIR / 128;
    int e = blockIdx.y / RB;
    int rb = blockIdx.y % RB;
    int c = g_cnt[e];
    int local0 = rb * 128;
    if (local0 >= c) return;
    int base = g_off[e];
    const float* Be = W + (size_t)e * K * N;

    __shared__ __align__(16) uint32_t As[2][16 * SA];
    __shared__ __align__(16) uint32_t Bs[2][16 * SB];
    __shared__ int rowtok[128];
    const int tid = threadIdx.x;
    if (tid < 128) {
        int lr = local0 + tid;
        rowtok[tid] = g_pair_tok[base + min(lr, c - 1)];
    }
    __syncthreads();

    const int lane = tid & 31, wid = tid >> 5;
    const int g = lane >> 2, t = lane & 3;
    const int warp_m = wid >> 2, warp_n = wid & 3;
    const int col0 = blockIdx.x * 128;

    float4 va[2], vb[2];
    auto loadA = [&](int k0) {
#pragma unroll
        for (int l = 0; l < 2; l++) {
            int f = tid + l * 256;
            int row = f >> 2, kc = (f & 3) * 4;
            va[l] = *(const float4*)(flat + (size_t)rowtok[row] * K + k0 + kc);
        }
    };
    auto loadB = [&](int k0) {
#pragma unroll
        for (int l = 0; l < 2; l++) {
            int f = tid + l * 256;
            int r = f >> 5, nc = (f & 31) * 4;
            vb[l] = *(const float4*)(Be + (size_t)(k0 + r) * N + col0 + nc);
        }
    };
    auto stage = [&](int buf) {
#pragma unroll
        for (int l = 0; l < 2; l++) {
            int f = tid + l * 256;
            int row = f >> 2, kc = (f & 3) * 4;
            As[buf][(kc + 0) * SA + row] = f2tf32(va[l].x);
            As[buf][(kc + 1) * SA + row] = f2tf32(va[l].y);
            As[buf][(kc + 2) * SA + row] = f2tf32(va[l].z);
            As[buf][(kc + 3) * SA + row] = f2tf32(va[l].w);
        }
#pragma unroll
        for (int l = 0; l < 2; l++) {
            int f = tid + l * 256;
            int r = f >> 5, nc = (f & 31) * 4;
            uint4 u = make_uint4(f2tf32(vb[l].x), f2tf32(vb[l].y),
                                 f2tf32(vb[l].z), f2tf32(vb[l].w));
            *(uint4*)&Bs[buf][r * SB + nc] = u;
        }
    };

    float d[4][4][4] = {};
    const int NIT = K / 16;
    loadA(0); loadB(0);
    stage(0);
    __syncthreads();
    int buf = 0;
    for (int it = 0; it < NIT; it++) {
        if (it + 1 < NIT) { loadA((it + 1) * 16); loadB((it + 1) * 16); }
        warp_compute16(As[buf], Bs[buf], d, warp_m * 64, warp_n * 32, g, t);
        if (it + 1 < NIT) {
            stage(buf ^ 1);
            __syncthreads();
            buf ^= 1;
        }
    }

    const int row_base = warp_m * 64, col_base = col0 + warp_n * 32;
#pragma unroll
    for (int i = 0; i < 4; i++)
#pragma unroll
        for (int j = 0; j < 4; j++) {
            int lr0 = local0 + row_base + i * 16 + g;
            int cc = col_base + j * 8 + 2 * t;
            if (lr0 < c)
                *(float2*)&C[(size_t)(base + lr0) * N + cc] =
                    make_float2(d[i][j][0], d[i][j][1]);
            if (lr0 + 8 < c)
                *(float2*)&C[(size_t)(base + lr0 + 8) * N + cc] =
                    make_float2(d[i][j][2], d[i][j][3]);
        }
}

// ---------------- expert GEMM NT: g_ey[r,n] = sum_k g_eh1[r,k] * W[e][n,k] ----------------
__global__ __launch_bounds__(256) void mma_expert_nt(const float* __restrict__ W,
                                                     int K, int N) {
    const float* act = g_eh1;
    float* C = g_ey;
    const int RB = NPAIR / 128;
    int e = blockIdx.y / RB;
    int rb = blockIdx.y % RB;
    int c = g_cnt[e];
    int local0 = rb * 128;
    if (local0 >= c) return;
    int base = g_off[e];
    const float* Be = W + (size_t)e * N * K;

    __shared__ __align__(16) uint32_t As[2][16 * SA];
    __shared__ __align__(16) uint32_t Bs[2][16 * SB];
    const int tid = threadIdx.x;
    const int lane = tid & 31, wid = tid >> 5;
    const int g = lane >> 2, t = lane & 3;
    const int warp_m = wid >> 2, warp_n = wid & 3;
    const int col0 = blockIdx.x * 128;

    float4 va[2], vb[2];
    auto loadA = [&](int k0) {
#pragma unroll
        for (int l = 0; l < 2; l++) {
            int f = tid + l * 256;
            int row = f >> 2, kc = (f & 3) * 4;
            int gr = base + min(local0 + row, c - 1);
            va[l] = *(const float4*)(act + (size_t)gr * K + k0 + kc);
        }
    };
    auto loadB = [&](int k0) {
#pragma unroll
        for (int l = 0; l < 2; l++) {
            int f = tid + l * 256;
            int n = f >> 2, kc = (f & 3) * 4;
            vb[l] = *(const float4*)(Be + (size_t)(col0 + n) * K + k0 + kc);
        }
    };
    auto stage = [&](int buf) {
#pragma unroll
        for (int l = 0; l < 2; l++) {
            int f = tid + l * 256;
            int row = f >> 2, kc = (f & 3) * 4;
            As[buf][(kc + 0) * SA + row] = f2tf32(va[l].x);
            As[buf][(kc + 1) * SA + row] = f2tf32(va[l].y);
            As[buf][(kc + 2) * SA + row] = f2tf32(va[l].z);
            As[buf][(kc + 3) * SA + row] = f2tf32(va[l].w);
        }
#pragma unroll
        for (int l = 0; l < 2; l++) {
            int f = tid + l * 256;
            int n = f >> 2, kc = (f & 3) * 4;
            Bs[buf][(kc + 0) * SB + n] = f2tf32(vb[l].x);
            Bs[buf][(kc + 1) * SB + n] = f2tf32(vb[l].y);
            Bs[buf][(kc + 2) * SB + n] = f2tf32(vb[l].z);
            Bs[buf][(kc + 3) * SB + n] = f2tf32(vb[l].w);
        }
    };

    float d[4][4][4] = {};
    const int NIT = K / 16;
    loadA(0); loadB(0);
    stage(0);
    __syncthreads();
    int buf = 0;
    for (int it = 0; it < NIT; it++) {
        if (it + 1 < NIT) { loadA((it + 1) * 16); loadB((it + 1) * 16); }
        warp_compute16(As[buf], Bs[buf], d, warp_m * 64, warp_n * 32, g, t);
        if (it + 1 < NIT) {
            stage(buf ^ 1);
            __syncthreads();
            buf ^= 1;
        }
    }

    const int row_base = warp_m * 64, col_base = col0 + warp_n * 32;
#pragma unroll
    for (int i = 0; i < 4; i++)
#pragma unroll
        for (int j = 0; j < 4; j++) {
            int lr0 = local0 + row_base + i * 16 + g;
            int cc = col_base + j * 8 + 2 * t;
            if (lr0 < c)
                *(float2*)&C[(size_t)(base + lr0) * N + cc] =
                    make_float2(d[i][j][0], d[i][j][1]);
            if (lr0 + 8 < c)
                *(float2*)&C[(size_t)(base + lr0 + 8) * N + cc] =
                    make_float2(d[i][j][2], d[i][j][3]);
        }
}

// ---------------- index dtype detection ----------------
__global__ void detect_idx_kernel(const int* __restrict__ idx32) {
    __shared__ int any;
    if (threadIdx.x == 0) any = 0;
    __syncthreads();
    int loc = 0;
    for (int i = threadIdx.x; i < NMOE_L * NPAIR; i += blockDim.x)
        if (i & 1) loc |= idx32[i];
    if (loc) atomicOr(&any, 1);
    __syncthreads();
    if (threadIdx.x == 0) g_idx_is32 = (any != 0);
}

// ---------------- elementwise / norm / attention helpers ----------------
__global__ void rmsnorm_kernel(const float* xext, int xsel,
                               const float* __restrict__ g, int ysel) {
    const float* x = rsel(xext, xsel);
    float* y = g_ptab[ysel];
    int r = blockIdx.x, t = threadIdx.x;
    const float* xr = x + (size_t)r * DIMM;
    float s = 0.f;
    for (int i = t; i < DIMM; i += 256) { float v = xr[i]; s += v * v; }
    __shared__ float red[8];
    for (int o = 16; o; o >>= 1) s += __shfl_xor_sync(~0u, s, o);
    if ((t & 31) == 0) red[t >> 5] = s;
    __syncthreads();
    __shared__ float tot;
    if (t == 0) {
        float v = 0.f;
        for (int i = 0; i < 8; i++) v += red[i];
        tot = rsqrtf(v / DIMM + 1e-6f);
    }
    __syncthreads();
    float rr = tot;
    float* yr = y + (size_t)r * DIMM;
    for (int i = t; i < DIMM; i += 256) yr[i] = xr[i] * rr * g[i];
}

__global__ void add_kernel(int asel, const float* bext, int bsel,
                           float* cext, int csel, int n) {
    const float* a = (const float*)g_ptab[asel];
    const float* b = rsel(bext, bsel);
    float* c = wsel(cext, csel);
    int i = blockIdx.x * blockDim.x + threadIdx.x;
    if (i < n) c[i] = a[i] + b[i];
}

__global__ void swiglu_kernel(int H, int total) {
    int i = blockIdx.x * blockDim.x + threadIdx.x;
    if (i >= total) return;
    int r = i / H, cidx = i - r * H;
    float a = g_u[(size_t)r * 2 * H + cidx];
    float b = g_u[(size_t)r * 2 * H + H + cidx];
    g_hh[i] = a / (1.f + expf(-a)) * b;
}

__global__ void swiglu_pair_kernel(int total) {
    int i = blockIdx.x * blockDim.x + threadIdx.x;
    if (i >= total) return;
    float a = g_eh1[i], b = g_eh2[i];
    g_eh1[i] = a / (1.f + expf(-a)) * b;
}

__global__ void doc_start_kernel(const int* __restrict__ doc) {
    int s = blockIdx.x * blockDim.x + threadIdx.x;
    if (s >= S_LEN) return;
    int v = doc[s];
    int lo = 0, hi = s;
    while (lo < hi) { int mid = (lo + hi) >> 1; if (doc[mid] < v) lo = mid + 1; else hi = mid; }
    g_dstart[s] = lo;
}

__global__ void rotary_kernel() {
    int s = blockIdx.x, h = blockIdx.y, i = threadIdx.x;  // i in [0,32)
    double invf = pow(10000.0, -((double)(2 * i)) / (double)HEADD);
    double fr = (double)s * invf;
    float c = (float)cos(fr), sn = (float)sin(fr);
    float* q = g_qkv + (size_t)s * 3 * DIMM + h * HEADD;
    float* k = q + DIMM;
    float x1 = q[i], x2 = q[i + 32];
    q[i] = x1 * c + x2 * sn; q[i + 32] = -x1 * sn + x2 * c;
    x1 = k[i]; x2 = k[i + 32];
    k[i] = x1 * c + x2 * sn; k[i + 32] = -x1 * sn + x2 * c;
}

// flash-style attention: block = (64 queries, 1 head); 1 thread per query.
__global__ void flash_kernel() {
    int h = blockIdx.y;
    int q0 = blockIdx.x * 64;
    int t = threadIdx.x;
    int sq = q0 + t;
    __shared__ float Ks[64][64];
    __shared__ float Vs[64][64];
    float qreg[64];
    const float* qp = g_qkv + (size_t)sq * 3 * DIMM + h * HEADD;
#pragma unroll
    for (int d = 0; d < 64; d++) qreg[d] = qp[d];
    float m = -1e30f, l = 0.f;
    float acc[64];
#pragma unroll
    for (int d = 0; d < 64; d++) acc[d] = 0.f;
    int ds = g_dstart[sq];
    int t0 = g_dstart[q0] >> 6;
    for (int kt = t0; kt <= (int)blockIdx.x; kt++) {
        int kbase = kt * 64;
        for (int idx = t; idx < 64 * 64; idx += 64) {
            int r = idx >> 6, d = idx & 63;
            const float* kv = g_qkv + (size_t)(kbase + r) * 3 * DIMM + h * HEADD + d;
            Ks[r][d] = kv[DIMM];
            Vs[r][d] = kv[2 * DIMM];
        }
        __syncthreads();
        int jmax = min(63, sq - kbase);
        int jmin = max(0, ds - kbase);
        for (int j = jmin; j <= jmax; j++) {
            float s0 = 0.f, s1 = 0.f, s2 = 0.f, s3 = 0.f;
#pragma unroll
            for (int d = 0; d < 64; d += 4) {
                s0 += qreg[d] * Ks[j][d];
                s1 += qreg[d + 1] * Ks[j][d + 1];
                s2 += qreg[d + 2] * Ks[j][d + 2];
                s3 += qreg[d + 3] * Ks[j][d + 3];
            }
            float s = (s0 + s1 + s2 + s3) * 0.125f;
            float mn = fmaxf(m, s);
            float corr = __expf(m - mn);
            float p = __expf(s - mn);
            l = l * corr + p;
#pragma unroll
            for (int d = 0; d < 64; d++) acc[d] = acc[d] * corr + p * Vs[j][d];
            m = mn;
        }
        __syncthreads();
    }
    float inv = 1.f / l;
    float* op = g_attn + (size_t)sq * DIMM + h * HEADD;
#pragma unroll
    for (int d = 0; d < 64; d++) op[d] = acc[d] * inv;
}

// ---------------- MoE routing ----------------
__global__ void tv_kernel(const float* __restrict__ tkeys) {
    int n = blockIdx.x;
    int w = threadIdx.x >> 5, lane = threadIdx.x & 31;
    const float* xr = g_xf + (size_t)n * DIMM;
    float s = 0.f;
    for (int d = lane; d < DIMM; d += 32) s += xr[d] * tkeys[d * LEXP + w];
    for (int o = 16; o; o >>= 1) s += __shfl_xor_sync(~0u, s, o);
    if (lane == 0) g_tv[n * LEXP + w] = s;
}

__global__ void zero_cnt_kernel() {
    if (threadIdx.x < LEXP) g_cnt[threadIdx.x] = 0;
}

__global__ void route1_kernel(const int* __restrict__ idx32, int off,
                              const float* __restrict__ vals,
                              const float* __restrict__ rbias) {
    int n = blockIdx.x * blockDim.x + threadIdx.x;
    if (n >= S_LEN) return;
    int is32 = g_idx_is32;
    float sc[TOPKK]; int e[TOPKK];
    float sum = 0.f;
#pragma unroll
    for (int k = 0; k < TOPKK; k++) {
        int elem = off + n * TOPKK + k;
        int ei = is32 ? idx32[elem] : idx32[2 * elem];  // int64 LE: low word
        e[k] = min(max(ei, 0), LEXP - 1);
        float v = vals[(size_t)n * TOPKK + k] + g_tv[n * LEXP + e[k]] + rbias[e[k]];
        sc[k] = 1.f / (1.f + expf(-v));
        sum += sc[k];
    }
#pragma unroll
    for (int k = 0; k < TOPKK; k++) {
        g_route_e[n * TOPKK + k] = e[k];
        g_route_sc[n * TOPKK + k] = sc[k] / sum;
        atomicAdd(&g_cnt[e[k]], 1);
    }
}

__global__ void scan_kernel() {
    int o = 0;
    for (int e = 0; e < LEXP; e++) { g_off[e] = o; o += g_cnt[e]; g_fill[e] = 0; }
}

__global__ void route2_kernel() {
    int n = blockIdx.x * blockDim.x + threadIdx.x;
    if (n >= S_LEN) return;
#pragma unroll
    for (int k = 0; k < TOPKK; k++) {
        int e = g_route_e[n * TOPKK + k];
        int slot = atomicAdd(&g_fill[e], 1);
        int pos = g_off[e] + slot;
        g_pair_tok[pos] = n;
        g_pair_pos[n * TOPKK + k] = pos;
    }
}

__global__ void moe_final_kernel() {
    int i = blockIdx.x * blockDim.x + threadIdx.x;
    if (i >= S_LEN * DIMM) return;
    int n = i >> 10, d = i & 1023;
    int p0 = g_pair_pos[2 * n], p1 = g_pair_pos[2 * n + 1];
    float y = g_route_sc[2 * n] * g_ey[(size_t)p0 * DIMM + d]
            + g_route_sc[2 * n + 1] * g_ey[(size_t)p1 * DIMM + d];
    g_xbuf[i] = y + g_ffn[i] + g_xi[i];
}

// ---------------- host orchestration ----------------
extern "C" void kernel_launch(void* const* d_in, const int* in_sizes, int n_in,
                              void* d_out, int out_size) {
    const float* x       = (const float*)d_in[0];
    const int*   doc     = (const int*)d_in[1];
    const int*   idx32   = (const int*)d_in[2];
    const float* values  = (const float*)d_in[3];
    const float* daw     = (const float*)d_in[4];
    const float* dao     = (const float*)d_in[5];
    const float* dup     = (const float*)d_in[6];
    const float* ddown   = (const float*)d_in[7];
    const float* dag     = (const float*)d_in[8];
    const float* dfg     = (const float*)d_in[9];
    const float* mawp    = (const float*)d_in[10];
    const float* maop    = (const float*)d_in[11];
    const float* magp    = (const float*)d_in[12];
    const float* mfgp    = (const float*)d_in[13];
    const float* experts = (const float*)d_in[14];
    const float* mtk     = (const float*)d_in[15];
    const float* rbias   = (const float*)d_in[16];
    const float* sup     = (const float*)d_in[17];
    const float* sdown   = (const float*)d_in[18];

    const int ND = S_LEN * DIMM;

    init_ptab_kernel<<<1, 32>>>();
    detect_idx_kernel<<<1, 256>>>(idx32);
    doc_start_kernel<<<(S_LEN + 255) / 256, 256>>>(doc);

    auto gemm = [&](int Asel, const float* B, int Csel, int M, int N, int K) {
        dim3 grid(N / 128, M / 128);
        mma_gemm_nn<<<grid, 256>>>(Asel, B, Csel, M, N, K);
    };
    auto attn_block = [&](const float* Xext, int Xsel, const float* aw,
                          const float* ao, const float* ag) {
        rmsnorm_kernel<<<S_LEN, 256>>>(Xext, Xsel, ag, SEL_XN);
        gemm(SEL_XN, aw, SEL_QKV, S_LEN, 3 * DIMM, DIMM);
        rotary_kernel<<<dim3(S_LEN, NHEADS), 32>>>();
        flash_kernel<<<dim3(S_LEN / 64, NHEADS), 64>>>();
        gemm(SEL_ATTN, ao, SEL_PROJ, S_LEN, DIMM, DIMM);
        add_kernel<<<(ND + 255) / 256, 256>>>(SEL_PROJ, Xext, Xsel, nullptr, SEL_XI, ND);
    };

    // ---- dense layer 0 ----
    {
        int li = 0;
        attn_block(x, -1, daw + (size_t)li * DIMM * 3 * DIMM,
                   dao + (size_t)li * DIMM * DIMM, dag + (size_t)li * DIMM);
        rmsnorm_kernel<<<S_LEN, 256>>>(nullptr, SEL_XI, dfg + (size_t)li * DIMM, SEL_XF);
        gemm(SEL_XF, dup + (size_t)li * DIMM * 2 * FFN_HH, SEL_U, S_LEN, 2 * FFN_HH, DIMM);
        swiglu_kernel<<<(S_LEN * FFN_HH + 255) / 256, 256>>>(FFN_HH, S_LEN * FFN_HH);
        gemm(SEL_HH, ddown + (size_t)li * FFN_HH * DIMM, SEL_FFN, S_LEN, DIMM, FFN_HH);
        add_kernel<<<(ND + 255) / 256, 256>>>(SEL_FFN, nullptr, SEL_XI, nullptr, SEL_XBUF, ND);
    }

    // ---- MoE layers ----
    for (int li = 0; li < 2; li++) {
        attn_block(nullptr, SEL_XBUF, mawp + (size_t)li * DIMM * 3 * DIMM,
                   maop + (size_t)li * DIMM * DIMM, magp + (size_t)li * DIMM);
        rmsnorm_kernel<<<S_LEN, 256>>>(nullptr, SEL_XI, mfgp + (size_t)li * DIMM, SEL_XF);
        tv_kernel<<<S_LEN, 256>>>(mtk + (size_t)li * DIMM * LEXP);
        zero_cnt_kernel<<<1, 32>>>();
        route1_kernel<<<(S_LEN + 255) / 256, 256>>>(idx32, li * NPAIR,
                                                    values + (size_t)li * NPAIR,
                                                    rbias + (size_t)li * LEXP);
        scan_kernel<<<1, 1>>>();
        route2_kernel<<<(S_LEN + 255) / 256, 256>>>();
        const float* eb = experts + (size_t)li * 3 * LEXP * DIMM * DIM_EE;
        dim3 eg_up(DIM_EE / 128, LEXP * (NPAIR / 128));
        mma_expert_nn<<<eg_up, 256>>>(eb, 0, DIMM, DIM_EE);
        mma_expert_nn<<<eg_up, 256>>>(eb + (size_t)LEXP * DIMM * DIM_EE, 1, DIMM, DIM_EE);
        swiglu_pair_kernel<<<(NPAIR * DIM_EE + 255) / 256, 256>>>(NPAIR * DIM_EE);
        dim3 eg_dn(DIMM / 128, LEXP * (NPAIR / 128));
        mma_expert_nt<<<eg_dn, 256>>>(eb + (size_t)2 * LEXP * DIMM * DIM_EE, DIM_EE, DIMM);
        // shared expert
        gemm(SEL_XF, sup + (size_t)li * DIMM * 2 * DIM_SS, SEL_U, S_LEN, 2 * DIM_SS, DIMM);
        swiglu_kernel<<<(S_LEN * DIM_SS + 255) / 256, 256>>>(DIM_SS, S_LEN * DIM_SS);
        gemm(SEL_HH, sdown + (size_t)li * DIM_SS * DIMM, SEL_FFN, S_LEN, DIMM, DIM_SS);
        moe_final_kernel<<<(ND + 255) / 256, 256>>>();
    }

    // ---- dense layer 1 (writes d_out) ----
    {
        int li = 1;
        attn_block(nullptr, SEL_XBUF, daw + (size_t)li * DIMM * 3 * DIMM,
                   dao + (size_t)li * DIMM * DIMM, dag + (size_t)li * DIMM);
        rmsnorm_kernel<<<S_LEN, 256>>>(nullptr, SEL_XI, dfg + (size_t)li * DIMM, SEL_XF);
        gemm(SEL_XF, dup + (size_t)li * DIMM * 2 * FFN_HH, SEL_U, S_LEN, 2 * FFN_HH, DIMM);
        swiglu_kernel<<<(S_LEN * FFN_HH + 255) / 256, 256>>>(FFN_HH, S_LEN * FFN_HH);
        gemm(SEL_HH, ddown + (size_t)li * FFN_HH * DIMM, SEL_FFN, S_LEN, DIMM, FFN_HH);
        add_kernel<<<(ND + 255) / 256, 256>>>(SEL_FFN, nullptr, SEL_XI, (float*)d_out, -1, ND);
    }
}

// round 5
// speedup vs baseline: 2.2182x; 1.0225x over previous
#include <cuda_runtime.h>
#include <cuda_bf16.h>
#include <math.h>
#include <stdint.h>

#define S_LEN 2048
#define DIMM 1024
#define NHEADS 16
#define HEADD 64
#define FFN_HH 4096
#define LEXP 8
#define TOPKK 2
#define DIM_EE 512
#define DIM_SS 1024
#define NPAIR (S_LEN*TOPKK)
#define NMOE_L 2

// ---------------- scratch (device globals; no allocation allowed) ----------------
__device__ float g_xn[S_LEN*DIMM];
__device__ float g_qkv[S_LEN*3*DIMM];
__device__ float g_attn[S_LEN*DIMM];
__device__ float g_proj[S_LEN*DIMM];
__device__ float g_xi[S_LEN*DIMM];
__device__ float g_xf[S_LEN*DIMM];
__device__ float g_u[S_LEN*2*FFN_HH];
__device__ float g_hh[S_LEN*FFN_HH];
__device__ float g_ffn[S_LEN*DIMM];
__device__ float g_xbuf[S_LEN*DIMM];
__device__ float g_tv[S_LEN*LEXP];
__device__ int   g_dstart[S_LEN];
__device__ int   g_route_e[NPAIR];
__device__ float g_route_sc[NPAIR];
__device__ int   g_pair_tok[NPAIR];
__device__ int   g_pair_pos[NPAIR];
__device__ int   g_cnt[LEXP];
__device__ int   g_off[LEXP];
__device__ int   g_fill[LEXP];
__device__ int   g_idx_is32;
__device__ float g_eh1[NPAIR*DIM_EE];
__device__ float g_eh2[NPAIR*DIM_EE];
__device__ float g_ey[NPAIR*DIMM];

#define SEL_XN   0
#define SEL_QKV  1
#define SEL_ATTN 2
#define SEL_PROJ 3
#define SEL_XI   4
#define SEL_XF   5
#define SEL_U    6
#define SEL_HH   7
#define SEL_FFN  8
#define SEL_XBUF 9
__device__ float* g_ptab[10];

__global__ void init_ptab_kernel() {
    if (threadIdx.x == 0) {
        g_ptab[SEL_XN]   = g_xn;
        g_ptab[SEL_QKV]  = g_qkv;
        g_ptab[SEL_ATTN] = g_attn;
        g_ptab[SEL_PROJ] = g_proj;
        g_ptab[SEL_XI]   = g_xi;
        g_ptab[SEL_XF]   = g_xf;
        g_ptab[SEL_U]    = g_u;
        g_ptab[SEL_FFN]  = g_ffn;
        g_ptab[SEL_HH]   = g_hh;
        g_ptab[SEL_XBUF] = g_xbuf;
    }
}

__device__ __forceinline__ const float* rsel(const float* ext, int sel) {
    return sel >= 0 ? (const float*)g_ptab[sel] : ext;
}
__device__ __forceinline__ float* wsel(float* ext, int sel) {
    return sel >= 0 ? g_ptab[sel] : ext;
}

// ---------------- TF32 MMA helpers ----------------
__device__ __forceinline__ uint32_t f2tf32(float f) {
    uint32_t u;
    asm("cvt.rna.tf32.f32 %0, %1;" : "=r"(u) : "f"(f));
    return u;
}

__device__ __forceinline__ void mma_tf32(float* d, const uint32_t* a, const uint32_t* b) {
    asm volatile(
        "mma.sync.aligned.m16n8k8.row.col.f32.tf32.tf32.f32 "
        "{%0,%1,%2,%3}, {%4,%5,%6,%7}, {%8,%9}, {%0,%1,%2,%3};\n"
        : "+f"(d[0]), "+f"(d[1]), "+f"(d[2]), "+f"(d[3])
        : "r"(a[0]), "r"(a[1]), "r"(a[2]), "r"(a[3]), "r"(b[0]), "r"(b[1]));
}

#define SA 136   // smem row stride (words); 136 % 32 == 8 -> conflict-free frag loads
#define SB 136

// warp computes 64x32 using 16 k=8 MMAs per k8-step, BK=16
__device__ __forceinline__ void warp_compute16(const uint32_t* As, const uint32_t* Bs,
                                               float (*d)[4][4], int mbase, int nbase,
                                               int g, int t) {
#pragma unroll
    for (int km = 0; km < 16; km += 8) {
        uint32_t af[4][4], bf[4][2];
#pragma unroll
        for (int i = 0; i < 4; i++) {
            const uint32_t* a0p = As + (km + t) * SA + mbase + i * 16 + g;
            const uint32_t* a1p = As + (km + t + 4) * SA + mbase + i * 16 + g;
            af[i][0] = a0p[0]; af[i][1] = a0p[8];
            af[i][2] = a1p[0]; af[i][3] = a1p[8];
        }
#pragma unroll
        for (int j = 0; j < 4; j++) {
            bf[j][0] = Bs[(km + t) * SB + nbase + j * 8 + g];
            bf[j][1] = Bs[(km + t + 4) * SB + nbase + j * 8 + g];
        }
#pragma unroll
        for (int i = 0; i < 4; i++)
#pragma unroll
            for (int j = 0; j < 4; j++)
                mma_tf32(d[i][j], af[i], bf[j]);
    }
}

// ---------------- TF32 GEMM: C = A(MxK,rm) @ B(KxN,rm) ----------------
__global__ __launch_bounds__(256, 2) void mma_gemm_nn(int Asel, const float* __restrict__ B,
                                                      int Csel, int M, int N, int K) {
    const float* A = (const float*)g_ptab[Asel];
    float* C = g_ptab[Csel];
    __shared__ __align__(16) uint32_t As[2][16 * SA];
    __shared__ __align__(16) uint32_t Bs[2][16 * SB];
    const int tid = threadIdx.x;
    const int lane = tid & 31, wid = tid >> 5;
    const int g = lane >> 2, t = lane & 3;
    const int warp_m = wid >> 2, warp_n = wid & 3;
    const int row0 = blockIdx.y * 128, col0 = blockIdx.x * 128;

    float4 va[2], vb[2];
    auto loadA = [&](int k0) {
#pragma unroll
        for (int l = 0; l < 2; l++) {
            int f = tid + l * 256;
            int row = f >> 2, kc = (f & 3) * 4;
            va[l] = *(const float4*)(A + (size_t)(row0 + row) * K + k0 + kc);
        }
    };
    auto loadB = [&](int k0) {
#pragma unroll
        for (int l = 0; l < 2; l++) {
            int f = tid + l * 256;
            int r = f >> 5, nc = (f & 31) * 4;
            vb[l] = *(const float4*)(B + (size_t)(k0 + r) * N + col0 + nc);
        }
    };
    auto stage = [&](int buf) {
#pragma unroll
        for (int l = 0; l < 2; l++) {
            int f = tid + l * 256;
            int row = f >> 2, kc = (f & 3) * 4;
            As[buf][(kc + 0) * SA + row] = f2tf32(va[l].x);
            As[buf][(kc + 1) * SA + row] = f2tf32(va[l].y);
            As[buf][(kc + 2) * SA + row] = f2tf32(va[l].z);
            As[buf][(kc + 3) * SA + row] = f2tf32(va[l].w);
        }
#pragma unroll
        for (int l = 0; l < 2; l++) {
            int f = tid + l * 256;
            int r = f >> 5, nc = (f & 31) * 4;
            uint4 u = make_uint4(f2tf32(vb[l].x), f2tf32(vb[l].y),
                                 f2tf32(vb[l].z), f2tf32(vb[l].w));
            *(uint4*)&Bs[buf][r * SB + nc] = u;
        }
    };

    float d[4][4][4] = {};
    const int NIT = K / 16;
    loadA(0); loadB(0);
    stage(0);
    __syncthreads();
    int buf = 0;
    for (int it = 0; it < NIT; it++) {
        if (it + 1 < NIT) { loadA((it + 1) * 16); loadB((it + 1) * 16); }
        warp_compute16(As[buf], Bs[buf], d, warp_m * 64, warp_n * 32, g, t);
        if (it + 1 < NIT) {
            stage(buf ^ 1);
            __syncthreads();
            buf ^= 1;
        }
    }

    const int row_base = row0 + warp_m * 64, col_base = col0 + warp_n * 32;
#pragma unroll
    for (int i = 0; i < 4; i++)
#pragma unroll
        for (int j = 0; j < 4; j++) {
            int r = row_base + i * 16 + g;
            int cc = col_base + j * 8 + 2 * t;
            *(float2*)&C[(size_t)r * N + cc]       = make_float2(d[i][j][0], d[i][j][1]);
            *(float2*)&C[(size_t)(r + 8) * N + cc] = make_float2(d[i][j][2], d[i][j][3]);
        }
}

// ---------------- expert GEMM NN (gathered rows from g_xf) ----------------
__global__ __launch_bounds__(256, 2) void mma_expert_nn(const float* __restrict__ W, int csel,
                                                        int K, int N) {
    const float* flat = g_xf;
    float* C = csel == 0 ? g_eh1 : g_eh2;
    const int RB = NPAIR / 128;
    int e = blockIdx.y / RB;
    int rb = blockIdx.y % RB;
    int c = g_cnt[e];
    int local0 = rb * 128;
    if (local0 >= c) return;
    int base = g_off[e];
    const float* Be = W + (size_t)e * K * N;

    __shared__ __align__(16) uint32_t As[2][16 * SA];
    __shared__ __align__(16) uint32_t Bs[2][16 * SB];
    __shared__ int rowtok[128];
    const int tid = threadIdx.x;
    if (tid < 128) {
        int lr = local0 + tid;
        rowtok[tid] = g_pair_tok[base + min(lr, c - 1)];
    }
    __syncthreads();

    const int lane = tid & 31, wid = tid >> 5;
    const int g = lane >> 2, t = lane & 3;
    const int warp_m = wid >> 2, warp_n = wid & 3;
    const int col0 = blockIdx.x * 128;

    float4 va[2], vb[2];
    auto loadA = [&](int k0) {
#pragma unroll
        for (int l = 0; l < 2; l++) {
            int f = tid + l * 256;
            int row = f >> 2, kc = (f & 3) * 4;
            va[l] = *(const float4*)(flat + (size_t)rowtok[row] * K + k0 + kc);
        }
    };
    auto loadB = [&](int k0) {
#pragma unroll
        for (int l = 0; l < 2; l++) {
            int f = tid + l * 256;
            int r = f >> 5, nc = (f & 31) * 4;
            vb[l] = *(const float4*)(Be + (size_t)(k0 + r) * N + col0 + nc);
        }
    };
    auto stage = [&](int buf) {
#pragma unroll
        for (int l = 0; l < 2; l++) {
            int f = tid + l * 256;
            int row = f >> 2, kc = (f & 3) * 4;
            As[buf][(kc + 0) * SA + row] = f2tf32(va[l].x);
            As[buf][(kc + 1) * SA + row] = f2tf32(va[l].y);
            As[buf][(kc + 2) * SA + row] = f2tf32(va[l].z);
            As[buf][(kc + 3) * SA + row] = f2tf32(va[l].w);
        }
#pragma unroll
        for (int l = 0; l < 2; l++) {
            int f = tid + l * 256;
            int r = f >> 5, nc = (f & 31) * 4;
            uint4 u = make_uint4(f2tf32(vb[l].x), f2tf32(vb[l].y),
                                 f2tf32(vb[l].z), f2tf32(vb[l].w));
            *(uint4*)&Bs[buf][r * SB + nc] = u;
        }
    };

    float d[4][4][4] = {};
    const int NIT = K / 16;
    loadA(0); loadB(0);
    stage(0);
    __syncthreads();
    int buf = 0;
    for (int it = 0; it < NIT; it++) {
        if (it + 1 < NIT) { loadA((it + 1) * 16); loadB((it + 1) * 16); }
        warp_compute16(As[buf], Bs[buf], d, warp_m * 64, warp_n * 32, g, t);
        if (it + 1 < NIT) {
            stage(buf ^ 1);
            __syncthreads();
            buf ^= 1;
        }
    }

    const int row_base = warp_m * 64, col_base = col0 + warp_n * 32;
#pragma unroll
    for (int i = 0; i < 4; i++)
#pragma unroll
        for (int j = 0; j < 4; j++) {
            int lr0 = local0 + row_base + i * 16 + g;
            int cc = col_base + j * 8 + 2 * t;
            if (lr0 < c)
                *(float2*)&C[(size_t)(base + lr0) * N + cc] =
                    make_float2(d[i][j][0], d[i][j][1]);
            if (lr0 + 8 < c)
                *(float2*)&C[(size_t)(base + lr0 + 8) * N + cc] =
                    make_float2(d[i][j][2], d[i][j][3]);
        }
}

// ---------------- expert GEMM NT: g_ey[r,n] = sum_k g_eh1[r,k] * W[e][n,k] ----------------
__global__ __launch_bounds__(256, 2) void mma_expert_nt(const float* __restrict__ W,
                                                        int K, int N) {
    const float* act = g_eh1;
    float* C = g_ey;
    const int RB = NPAIR / 128;
    int e = blockIdx.y / RB;
    int rb = blockIdx.y % RB;
    int c = g_cnt[e];
    int local0 = rb * 128;
    if (local0 >= c) return;
    int base = g_off[e];
    const float* Be = W + (size_t)e * N * K;

    __shared__ __align__(16) uint32_t As[2][16 * SA];
    __shared__ __align__(16) uint32_t Bs[2][16 * SB];
    const int tid = threadIdx.x;
    const int lane = tid & 31, wid = tid >> 5;
    const int g = lane >> 2, t = lane & 3;
    const int warp_m = wid >> 2, warp_n = wid & 3;
    const int col0 = blockIdx.x * 128;

    float4 va[2], vb[2];
    auto loadA = [&](int k0) {
#pragma unroll
        for (int l = 0; l < 2; l++) {
            int f = tid + l * 256;
            int row = f >> 2, kc = (f & 3) * 4;
            int gr = base + min(local0 + row, c - 1);
            va[l] = *(const float4*)(act + (size_t)gr * K + k0 + kc);
        }
    };
    auto loadB = [&](int k0) {
#pragma unroll
        for (int l = 0; l < 2; l++) {
            int f = tid + l * 256;
            int n = f >> 2, kc = (f & 3) * 4;
            vb[l] = *(const float4*)(Be + (size_t)(col0 + n) * K + k0 + kc);
        }
    };
    auto stage = [&](int buf) {
#pragma unroll
        for (int l = 0; l < 2; l++) {
            int f = tid + l * 256;
            int row = f >> 2, kc = (f & 3) * 4;
            As[buf][(kc + 0) * SA + row] = f2tf32(va[l].x);
            As[buf][(kc + 1) * SA + row] = f2tf32(va[l].y);
            As[buf][(kc + 2) * SA + row] = f2tf32(va[l].z);
            As[buf][(kc + 3) * SA + row] = f2tf32(va[l].w);
        }
#pragma unroll
        for (int l = 0; l < 2; l++) {
            int f = tid + l * 256;
            int n = f >> 2, kc = (f & 3) * 4;
            Bs[buf][(kc + 0) * SB + n] = f2tf32(vb[l].x);
            Bs[buf][(kc + 1) * SB + n] = f2tf32(vb[l].y);
            Bs[buf][(kc + 2) * SB + n] = f2tf32(vb[l].z);
            Bs[buf][(kc + 3) * SB + n] = f2tf32(vb[l].w);
        }
    };

    float d[4][4][4] = {};
    const int NIT = K / 16;
    loadA(0); loadB(0);
    stage(0);
    __syncthreads();
    int buf = 0;
    for (int it = 0; it < NIT; it++) {
        if (it + 1 < NIT) { loadA((it + 1) * 16); loadB((it + 1) * 16); }
        warp_compute16(As[buf], Bs[buf], d, warp_m * 64, warp_n * 32, g, t);
        if (it + 1 < NIT) {
            stage(buf ^ 1);
            __syncthreads();
            buf ^= 1;
        }
    }

    const int row_base = warp_m * 64, col_base = col0 + warp_n * 32;
#pragma unroll
    for (int i = 0; i < 4; i++)
#pragma unroll
        for (int j = 0; j < 4; j++) {
            int lr0 = local0 + row_base + i * 16 + g;
            int cc = col_base + j * 8 + 2 * t;
            if (lr0 < c)
                *(float2*)&C[(size_t)(base + lr0) * N + cc] =
                    make_float2(d[i][j][0], d[i][j][1]);
            if (lr0 + 8 < c)
                *(float2*)&C[(size_t)(base + lr0 + 8) * N + cc] =
                    make_float2(d[i][j][2], d[i][j][3]);
        }
}

// ---------------- index dtype detection ----------------
__global__ void detect_idx_kernel(const int* __restrict__ idx32) {
    __shared__ int any;
    if (threadIdx.x == 0) any = 0;
    __syncthreads();
    int loc = 0;
    for (int i = threadIdx.x; i < NMOE_L * NPAIR; i += blockDim.x)
        if (i & 1) loc |= idx32[i];
    if (loc) atomicOr(&any, 1);
    __syncthreads();
    if (threadIdx.x == 0) g_idx_is32 = (any != 0);
}

// ---------------- elementwise / norm / attention helpers ----------------
__global__ void rmsnorm_kernel(const float* xext, int xsel,
                               const float* __restrict__ g, int ysel) {
    const float* x = rsel(xext, xsel);
    float* y = g_ptab[ysel];
    int r = blockIdx.x, t = threadIdx.x;
    const float* xr = x + (size_t)r * DIMM;
    float s = 0.f;
    for (int i = t; i < DIMM; i += 256) { float v = xr[i]; s += v * v; }
    __shared__ float red[8];
    for (int o = 16; o; o >>= 1) s += __shfl_xor_sync(~0u, s, o);
    if ((t & 31) == 0) red[t >> 5] = s;
    __syncthreads();
    __shared__ float tot;
    if (t == 0) {
        float v = 0.f;
        for (int i = 0; i < 8; i++) v += red[i];
        tot = rsqrtf(v / DIMM + 1e-6f);
    }
    __syncthreads();
    float rr = tot;
    float* yr = y + (size_t)r * DIMM;
    for (int i = t; i < DIMM; i += 256) yr[i] = xr[i] * rr * g[i];
}

__global__ void add_kernel(int asel, const float* bext, int bsel,
                           float* cext, int csel, int n) {
    const float* a = (const float*)g_ptab[asel];
    const float* b = rsel(bext, bsel);
    float* c = wsel(cext, csel);
    int i = blockIdx.x * blockDim.x + threadIdx.x;
    if (i < n) c[i] = a[i] + b[i];
}

__global__ void swiglu_kernel(int H, int total) {
    int i = blockIdx.x * blockDim.x + threadIdx.x;
    if (i >= total) return;
    int r = i / H, cidx = i - r * H;
    float a = g_u[(size_t)r * 2 * H + cidx];
    float b = g_u[(size_t)r * 2 * H + H + cidx];
    g_hh[i] = a / (1.f + expf(-a)) * b;
}

__global__ void swiglu_pair_kernel(int total) {
    int i = blockIdx.x * blockDim.x + threadIdx.x;
    if (i >= total) return;
    float a = g_eh1[i], b = g_eh2[i];
    g_eh1[i] = a / (1.f + expf(-a)) * b;
}

__global__ void doc_start_kernel(const int* __restrict__ doc) {
    int s = blockIdx.x * blockDim.x + threadIdx.x;
    if (s >= S_LEN) return;
    int v = doc[s];
    int lo = 0, hi = s;
    while (lo < hi) { int mid = (lo + hi) >> 1; if (doc[mid] < v) lo = mid + 1; else hi = mid; }
    g_dstart[s] = lo;
}

__global__ void rotary_kernel() {
    int s = blockIdx.x, h = blockIdx.y, i = threadIdx.x;  // i in [0,32)
    double invf = pow(10000.0, -((double)(2 * i)) / (double)HEADD);
    double fr = (double)s * invf;
    float c = (float)cos(fr), sn = (float)sin(fr);
    float* q = g_qkv + (size_t)s * 3 * DIMM + h * HEADD;
    float* k = q + DIMM;
    float x1 = q[i], x2 = q[i + 32];
    q[i] = x1 * c + x2 * sn; q[i + 32] = -x1 * sn + x2 * c;
    x1 = k[i]; x2 = k[i + 32];
    k[i] = x1 * c + x2 * sn; k[i + 32] = -x1 * sn + x2 * c;
}

// flash-style attention: block = (64 queries, 1 head); 1 thread per query.
// Rescale-skip: only rescale the accumulator when the running max changes.
__global__ void flash_kernel() {
    int h = blockIdx.y;
    int q0 = blockIdx.x * 64;
    int t = threadIdx.x;
    int sq = q0 + t;
    __shared__ float Ks[64][64];
    __shared__ float Vs[64][64];
    float qreg[64];
    const float* qp = g_qkv + (size_t)sq * 3 * DIMM + h * HEADD;
#pragma unroll
    for (int d = 0; d < 64; d++) qreg[d] = qp[d];
    float m = -1e30f, l = 0.f;
    float acc[64];
#pragma unroll
    for (int d = 0; d < 64; d++) acc[d] = 0.f;
    int ds = g_dstart[sq];
    int t0 = g_dstart[q0] >> 6;
    for (int kt = t0; kt <= (int)blockIdx.x; kt++) {
        int kbase = kt * 64;
        for (int idx = t; idx < 64 * 64; idx += 64) {
            int r = idx >> 6, d = idx & 63;
            const float* kv = g_qkv + (size_t)(kbase + r) * 3 * DIMM + h * HEADD + d;
            Ks[r][d] = kv[DIMM];
            Vs[r][d] = kv[2 * DIMM];
        }
        __syncthreads();
        int jmax = min(63, sq - kbase);
        int jmin = max(0, ds - kbase);
        for (int j = jmin; j <= jmax; j++) {
            float s0 = 0.f, s1 = 0.f, s2 = 0.f, s3 = 0.f;
#pragma unroll
            for (int d = 0; d < 64; d += 4) {
                s0 += qreg[d] * Ks[j][d];
                s1 += qreg[d + 1] * Ks[j][d + 1];
                s2 += qreg[d + 2] * Ks[j][d + 2];
                s3 += qreg[d + 3] * Ks[j][d + 3];
            }
            float s = (s0 + s1 + s2 + s3) * 0.125f;
            if (s <= m) {
                float p = __expf(s - m);
                l += p;
#pragma unroll
                for (int d = 0; d < 64; d++) acc[d] += p * Vs[j][d];
            } else {
                float corr = __expf(m - s);
                l = l * corr + 1.f;
#pragma unroll
                for (int d = 0; d < 64; d++) acc[d] = acc[d] * corr + Vs[j][d];
                m = s;
            }
        }
        __syncthreads();
    }
    float inv = 1.f / l;
    float* op = g_attn + (size_t)sq * DIMM + h * HEADD;
#pragma unroll
    for (int d = 0; d < 64; d++) op[d] = acc[d] * inv;
}

// ---------------- MoE routing ----------------
__global__ void tv_kernel(const float* __restrict__ tkeys) {
    int n = blockIdx.x;
    int w = threadIdx.x >> 5, lane = threadIdx.x & 31;
    const float* xr = g_xf + (size_t)n * DIMM;
    float s = 0.f;
    for (int d = lane; d < DIMM; d += 32) s += xr[d] * tkeys[d * LEXP + w];
    for (int o = 16; o; o >>= 1) s += __shfl_xor_sync(~0u, s, o);
    if (lane == 0) g_tv[n * LEXP + w] = s;
}

__global__ void zero_cnt_kernel() {
    if (threadIdx.x < LEXP) g_cnt[threadIdx.x] = 0;
}

__global__ void route1_kernel(const int* __restrict__ idx32, int off,
                              const float* __restrict__ vals,
                              const float* __restrict__ rbias) {
    int n = blockIdx.x * blockDim.x + threadIdx.x;
    if (n >= S_LEN) return;
    int is32 = g_idx_is32;
    float sc[TOPKK]; int e[TOPKK];
    float sum = 0.f;
#pragma unroll
    for (int k = 0; k < TOPKK; k++) {
        int elem = off + n * TOPKK + k;
        int ei = is32 ? idx32[elem] : idx32[2 * elem];  // int64 LE: low word
        e[k] = min(max(ei, 0), LEXP - 1);
        float v = vals[(size_t)n * TOPKK + k] + g_tv[n * LEXP + e[k]] + rbias[e[k]];
        sc[k] = 1.f / (1.f + expf(-v));
        sum += sc[k];
    }
#pragma unroll
    for (int k = 0; k < TOPKK; k++) {
        g_route_e[n * TOPKK + k] = e[k];
        g_route_sc[n * TOPKK + k] = sc[k] / sum;
        atomicAdd(&g_cnt[e[k]], 1);
    }
}

__global__ void scan_kernel() {
    int o = 0;
    for (int e = 0; e < LEXP; e++) { g_off[e] = o; o += g_cnt[e]; g_fill[e] = 0; }
}

__global__ void route2_kernel() {
    int n = blockIdx.x * blockDim.x + threadIdx.x;
    if (n >= S_LEN) return;
#pragma unroll
    for (int k = 0; k < TOPKK; k++) {
        int e = g_route_e[n * TOPKK + k];
        int slot = atomicAdd(&g_fill[e], 1);
        int pos = g_off[e] + slot;
        g_pair_tok[pos] = n;
        g_pair_pos[n * TOPKK + k] = pos;
    }
}

__global__ void moe_final_kernel() {
    int i = blockIdx.x * blockDim.x + threadIdx.x;
    if (i >= S_LEN * DIMM) return;
    int n = i >> 10, d = i & 1023;
    int p0 = g_pair_pos[2 * n], p1 = g_pair_pos[2 * n + 1];
    float y = g_route_sc[2 * n] * g_ey[(size_t)p0 * DIMM + d]
            + g_route_sc[2 * n + 1] * g_ey[(size_t)p1 * DIMM + d];
    g_xbuf[i] = y + g_ffn[i] + g_xi[i];
}

// ---------------- host orchestration ----------------
extern "C" void kernel_launch(void* const* d_in, const int* in_sizes, int n_in,
                              void* d_out, int out_size) {
    const float* x       = (const float*)d_in[0];
    const int*   doc     = (const int*)d_in[1];
    const int*   idx32   = (const int*)d_in[2];
    const float* values  = (const float*)d_in[3];
    const float* daw     = (const float*)d_in[4];
    const float* dao     = (const float*)d_in[5];
    const float* dup     = (const float*)d_in[6];
    const float* ddown   = (const float*)d_in[7];
    const float* dag     = (const float*)d_in[8];
    const float* dfg     = (const float*)d_in[9];
    const float* mawp    = (const float*)d_in[10];
    const float* maop    = (const float*)d_in[11];
    const float* magp    = (const float*)d_in[12];
    const float* mfgp    = (const float*)d_in[13];
    const float* experts = (const float*)d_in[14];
    const float* mtk     = (const float*)d_in[15];
    const float* rbias   = (const float*)d_in[16];
    const float* sup     = (const float*)d_in[17];
    const float* sdown   = (const float*)d_in[18];

    const int ND = S_LEN * DIMM;

    init_ptab_kernel<<<1, 32>>>();
    detect_idx_kernel<<<1, 256>>>(idx32);
    doc_start_kernel<<<(S_LEN + 255) / 256, 256>>>(doc);

    auto gemm = [&](int Asel, const float* B, int Csel, int M, int N, int K) {
        dim3 grid(N / 128, M / 128);
        mma_gemm_nn<<<grid, 256>>>(Asel, B, Csel, M, N, K);
    };
    auto attn_block = [&](const float* Xext, int Xsel, const float* aw,
                          const float* ao, const float* ag) {
        rmsnorm_kernel<<<S_LEN, 256>>>(Xext, Xsel, ag, SEL_XN);
        gemm(SEL_XN, aw, SEL_QKV, S_LEN, 3 * DIMM, DIMM);
        rotary_kernel<<<dim3(S_LEN, NHEADS), 32>>>();
        flash_kernel<<<dim3(S_LEN / 64, NHEADS), 64>>>();
        gemm(SEL_ATTN, ao, SEL_PROJ, S_LEN, DIMM, DIMM);
        add_kernel<<<(ND + 255) / 256, 256>>>(SEL_PROJ, Xext, Xsel, nullptr, SEL_XI, ND);
    };

    // ---- dense layer 0 ----
    {
        int li = 0;
        attn_block(x, -1, daw + (size_t)li * DIMM * 3 * DIMM,
                   dao + (size_t)li * DIMM * DIMM, dag + (size_t)li * DIMM);
        rmsnorm_kernel<<<S_LEN, 256>>>(nullptr, SEL_XI, dfg + (size_t)li * DIMM, SEL_XF);
        gemm(SEL_XF, dup + (size_t)li * DIMM * 2 * FFN_HH, SEL_U, S_LEN, 2 * FFN_HH, DIMM);
        swiglu_kernel<<<(S_LEN * FFN_HH + 255) / 256, 256>>>(FFN_HH, S_LEN * FFN_HH);
        gemm(SEL_HH, ddown + (size_t)li * FFN_HH * DIMM, SEL_FFN, S_LEN, DIMM, FFN_HH);
        add_kernel<<<(ND + 255) / 256, 256>>>(SEL_FFN, nullptr, SEL_XI, nullptr, SEL_XBUF, ND);
    }

    // ---- MoE layers ----
    for (int li = 0; li < 2; li++) {
        attn_block(nullptr, SEL_XBUF, mawp + (size_t)li * DIMM * 3 * DIMM,
                   maop + (size_t)li * DIMM * DIMM, magp + (size_t)li * DIMM);
        rmsnorm_kernel<<<S_LEN, 256>>>(nullptr, SEL_XI, mfgp + (size_t)li * DIMM, SEL_XF);
        tv_kernel<<<S_LEN, 256>>>(mtk + (size_t)li * DIMM * LEXP);
        zero_cnt_kernel<<<1, 32>>>();
        route1_kernel<<<(S_LEN + 255) / 256, 256>>>(idx32, li * NPAIR,
                                                    values + (size_t)li * NPAIR,
                                                    rbias + (size_t)li * LEXP);
        scan_kernel<<<1, 1>>>();
        route2_kernel<<<(S_LEN + 255) / 256, 256>>>();
        const float* eb = experts + (size_t)li * 3 * LEXP * DIMM * DIM_EE;
        dim3 eg_up(DIM_EE / 128, LEXP * (NPAIR / 128));
        mma_expert_nn<<<eg_up, 256>>>(eb, 0, DIMM, DIM_EE);
        mma_expert_nn<<<eg_up, 256>>>(eb + (size_t)LEXP * DIMM * DIM_EE, 1, DIMM, DIM_EE);
        swiglu_pair_kernel<<<(NPAIR * DIM_EE + 255) / 256, 256>>>(NPAIR * DIM_EE);
        dim3 eg_dn(DIMM / 128, LEXP * (NPAIR / 128));
        mma_expert_nt<<<eg_dn, 256>>>(eb + (size_t)2 * LEXP * DIMM * DIM_EE, DIM_EE, DIMM);
        // shared expert
        gemm(SEL_XF, sup + (size_t)li * DIMM * 2 * DIM_SS, SEL_U, S_LEN, 2 * DIM_SS, DIMM);
        swiglu_kernel<<<(S_LEN * DIM_SS + 255) / 256, 256>>>(DIM_SS, S_LEN * DIM_SS);
        gemm(SEL_HH, sdown + (size_t)li * DIM_SS * DIMM, SEL_FFN, S_LEN, DIMM, DIM_SS);
        moe_final_kernel<<<(ND + 255) / 256, 256>>>();
    }

    // ---- dense layer 1 (writes d_out) ----
    {
        int li = 1;
        attn_block(nullptr, SEL_XBUF, daw + (size_t)li * DIMM * 3 * DIMM,
                   dao + (size_t)li * DIMM * DIMM, dag + (size_t)li * DIMM);
        rmsnorm_kernel<<<S_LEN, 256>>>(nullptr, SEL_XI, dfg + (size_t)li * DIMM, SEL_XF);
        gemm(SEL_XF, dup + (size_t)li * DIMM * 2 * FFN_HH, SEL_U, S_LEN, 2 * FFN_HH, DIMM);
        swiglu_kernel<<<(S_LEN * FFN_HH + 255) / 256, 256>>>(FFN_HH, S_LEN * FFN_HH);
        gemm(SEL_HH, ddown + (size_t)li * FFN_HH * DIMM, SEL_FFN, S_LEN, DIMM, FFN_HH);
        add_kernel<<<(ND + 255) / 256, 256>>>(SEL_FFN, nullptr, SEL_XI, (float*)d_out, -1, ND);
    }
}